// round 4
// baseline (speedup 1.0000x reference)
#include <cuda_runtime.h>
#include <cuda_bf16.h>

#define B_  16
#define LQ  256
#define LK  256
#define QD  256
#define HD  128
#define VD  128
#define KT  8     // k-rows per CTA (warp w handles k-row w)
#define TQ  32    // q-tile staged in smem

// Scratch for projected q/k (allocation-free rule: __device__ globals)
__device__ float g_qp[B_ * LQ * HD];
__device__ float g_kp[B_ * LK * HD];

__device__ __forceinline__ float tanh_fast(float x) {
    float y;
    asm("tanh.approx.f32 %0, %1;" : "=f"(y) : "f"(x));
    return y;
}
__device__ __forceinline__ unsigned long long pk2(float lo, float hi) {
    unsigned long long r;
    asm("mov.b64 %0, {%1, %2};" : "=l"(r) : "f"(lo), "f"(hi));
    return r;
}
__device__ __forceinline__ void upk2(unsigned long long v, float& lo, float& hi) {
    asm("mov.b64 {%0, %1}, %2;" : "=f"(lo), "=f"(hi) : "l"(v));
}
__device__ __forceinline__ void fma2(unsigned long long& d, unsigned long long a,
                                     unsigned long long b) {
    asm("fma.rn.f32x2 %0, %1, %2, %0;" : "+l"(d) : "l"(a), "l"(b));
}

// ============================================================================
// Kernel 1: qp = query @ Wq, kp = key @ Wk  (fp32, packed f32x2 FFMA)
// grid = (4096/32, 2), block = 256. BM=32, BN=128 (all H), BK=32.
// Thread: ty = t/32 picks 4 rows, tx = t%32 picks 4 cols. Rows packed in pairs
// into f32x2 accumulators -> 2x FMA throughput vs scalar FFMA.
// ============================================================================
__global__ __launch_bounds__(256) void proj_kernel(
    const float* __restrict__ q_in, const float* __restrict__ k_in,
    const float* __restrict__ Wq,   const float* __restrict__ Wk)
{
    const float* X = blockIdx.y ? k_in : q_in;
    const float* W = blockIdx.y ? Wk : Wq;
    float* Y       = blockIdx.y ? g_kp : g_qp;

    __shared__ float As[32][34];     // [k][row], pad 34 (even -> float2-aligned)
    __shared__ float Bs[32][128];    // [k][h]

    const int t   = threadIdx.x;
    const int tx  = t & 31;
    const int ty  = t >> 5;
    const int r0  = blockIdx.x * 32;

    unsigned long long acc[2][4];
    #pragma unroll
    for (int p = 0; p < 2; p++)
        #pragma unroll
        for (int j = 0; j < 4; j++) acc[p][j] = 0ull;

    for (int kb = 0; kb < QD; kb += 32) {
        __syncthreads();
        #pragma unroll
        for (int i = 0; i < 4; i++) {           // A tile 32x32 (transposed store)
            int flat = i * 256 + t;
            int r = flat >> 5, kk = flat & 31;
            As[kk][r] = X[(r0 + r) * QD + kb + kk];
        }
        #pragma unroll
        for (int i = 0; i < 16; i++) {          // B tile 32x128
            int flat = i * 256 + t;
            int kk = flat >> 7, h = flat & 127;
            Bs[kk][h] = W[(kb + kk) * HD + h];
        }
        __syncthreads();
        #pragma unroll
        for (int kk = 0; kk < 32; kk++) {
            float2 a0 = *(const float2*)&As[kk][ty * 4];       // rows pair 0 (bcast)
            float2 a1 = *(const float2*)&As[kk][ty * 4 + 2];   // rows pair 1 (bcast)
            float4 bv = *(const float4*)&Bs[kk][tx * 4];       // LDS.128, conflict-free
            unsigned long long ap0 = pk2(a0.x, a0.y);
            unsigned long long ap1 = pk2(a1.x, a1.y);
            unsigned long long b0 = pk2(bv.x, bv.x);
            unsigned long long b1 = pk2(bv.y, bv.y);
            unsigned long long b2 = pk2(bv.z, bv.z);
            unsigned long long b3 = pk2(bv.w, bv.w);
            fma2(acc[0][0], ap0, b0); fma2(acc[0][1], ap0, b1);
            fma2(acc[0][2], ap0, b2); fma2(acc[0][3], ap0, b3);
            fma2(acc[1][0], ap1, b0); fma2(acc[1][1], ap1, b1);
            fma2(acc[1][2], ap1, b2); fma2(acc[1][3], ap1, b3);
        }
    }

    #pragma unroll
    for (int p = 0; p < 2; p++) {
        float lo[4], hi[4];
        #pragma unroll
        for (int j = 0; j < 4; j++) upk2(acc[p][j], lo[j], hi[j]);
        int r = r0 + ty * 4 + 2 * p;
        *(float4*)&Y[r * HD + tx * 4]       = make_float4(lo[0], lo[1], lo[2], lo[3]);
        *(float4*)&Y[(r + 1) * HD + tx * 4] = make_float4(hi[0], hi[1], hi[2], hi[3]);
    }
}

// ============================================================================
// Kernel 2: scores + softmax(over q) + context.
// grid = B * (LK/KT) = 512 CTAs, 256 threads. Warp w owns k-row k0+w.
// Phase B (MUFU-bound): per h-step = LDS.32(qp) + LDS.64(kp,v) + FADD + TANH + FFMA
// Phase C: per-warp softmax over 256 q, writes attention.
// Phase D: context = attn @ value via float4 LDS of staged value tiles.
// qps ([HD][TQ+1] transposed+padded) and val_s ([TQ][VD]) share one buffer
// (disjoint in time) to stay under the 48KB static smem limit.
// ============================================================================
__global__ __launch_bounds__(256) void attn_kernel(
    const float* __restrict__ value, const float* __restrict__ vvec,
    float* __restrict__ ctx, float* __restrict__ attn)
{
    const int blk  = blockIdx.x;
    const int b    = blk >> 5;          // 32 k-tiles per batch
    const int k0   = (blk & 31) * KT;

    __shared__ float kv[KT][HD][2];                 // (kp, v) interleaved -> LDS.64
    __shared__ float S[KT][LQ];                     // score rows
    __shared__ __align__(16) float qbuf[HD * (TQ + 1)];  // qps / val_s overlay
    float (*qps)[TQ + 1] = (float(*)[TQ + 1])qbuf;
    float (*val_s)[VD]   = (float(*)[VD])qbuf;

    const int t    = threadIdx.x;
    const int w    = t >> 5;            // warp = local k index
    const int lane = t & 31;

    // stage kp rows + v, interleaved
    for (int idx = t; idx < KT * HD; idx += 256) {
        int k = idx >> 7, h = idx & 127;
        kv[k][h][0] = g_kp[(b * LK + k0 + k) * HD + h];
        kv[k][h][1] = vvec[h];
    }

    // ---- Phase B: scores ----
    const float* qp_b = g_qp + b * LQ * HD;
    for (int qt = 0; qt < LQ / TQ; qt++) {
        __syncthreads();
        for (int idx = t; idx < TQ * HD; idx += 256) {  // stage qp tile transposed
            int q = idx >> 7, h = idx & 127;
            qps[h][q] = qp_b[(qt * TQ + q) * HD + h];
        }
        __syncthreads();
        float sc = 0.f;
        #pragma unroll 32
        for (int h = 0; h < HD; h++) {
            float2 kvv = *(const float2*)&kv[w][h][0];       // broadcast LDS.64
            sc += tanh_fast(qps[h][lane] + kvv.x) * kvv.y;   // 1 MUFU / element
        }
        S[w][qt * TQ + lane] = sc;
    }
    __syncwarp();

    // ---- Phase C: softmax over q (row w handled by warp w) ----
    float vals[8];
    float m = -1e30f;
    #pragma unroll
    for (int i = 0; i < 8; i++) {
        vals[i] = S[w][lane + 32 * i];
        m = fmaxf(m, vals[i]);
    }
    #pragma unroll
    for (int o = 16; o > 0; o >>= 1) m = fmaxf(m, __shfl_xor_sync(0xffffffffu, m, o));
    float sum = 0.f;
    #pragma unroll
    for (int i = 0; i < 8; i++) { vals[i] = __expf(vals[i] - m); sum += vals[i]; }
    #pragma unroll
    for (int o = 16; o > 0; o >>= 1) sum += __shfl_xor_sync(0xffffffffu, sum, o);
    float inv = 1.0f / sum;
    float* attn_row = attn + (b * LK + k0 + w) * LQ;
    #pragma unroll
    for (int i = 0; i < 8; i++) {
        float p = vals[i] * inv;
        S[w][lane + 32 * i] = p;
        attn_row[lane + 32 * i] = p;
    }

    // ---- Phase D: context[k][vd] = sum_q P[k][q] * value[b][q][vd] ----
    float4 acc = make_float4(0.f, 0.f, 0.f, 0.f);
    const float* val_b = value + b * LQ * VD;
    for (int qt = 0; qt < LQ / TQ; qt++) {
        __syncthreads();                 // protects qbuf overlay + tile reuse
        #pragma unroll
        for (int i = 0; i < 4; i++) {    // stage value tile 32x128, float4
            int flat4 = i * 256 + t;
            int q = flat4 >> 5, c4 = flat4 & 31;
            *(float4*)&val_s[q][c4 * 4] =
                *(const float4*)&val_b[(qt * TQ + q) * VD + c4 * 4];
        }
        __syncthreads();
        #pragma unroll
        for (int q = 0; q < TQ; q++) {
            float p = S[w][qt * TQ + q];                       // broadcast
            float4 vv = *(const float4*)&val_s[q][lane * 4];   // LDS.128
            acc.x += p * vv.x; acc.y += p * vv.y;
            acc.z += p * vv.z; acc.w += p * vv.w;
        }
    }
    *(float4*)&ctx[(b * LK + k0 + w) * VD + lane * 4] = acc;
}

// ============================================================================
// Launch: inputs (metadata order): query, key, value, Wq, Wk, v
// d_out = context [B,LK,VD] followed by attention [B,LK,LQ] (tuple order)
// ============================================================================
extern "C" void kernel_launch(void* const* d_in, const int* in_sizes, int n_in,
                              void* d_out, int out_size)
{
    const float* query = (const float*)d_in[0];
    const float* key_t = (const float*)d_in[1];
    const float* value = (const float*)d_in[2];
    const float* Wq    = (const float*)d_in[3];
    const float* Wk    = (const float*)d_in[4];
    const float* vvec  = (const float*)d_in[5];

    float* ctx  = (float*)d_out;
    float* attn = ctx + (size_t)B_ * LK * VD;

    dim3 g1(B_ * LQ / 32, 2);
    proj_kernel<<<g1, 256>>>(query, key_t, Wq, Wk);
    attn_kernel<<<B_ * (LK / KT), 256>>>(value, vvec, ctx, attn);
}

// round 5
// speedup vs baseline: 1.1909x; 1.1909x over previous
#include <cuda_runtime.h>
#include <cuda_bf16.h>

#define B_  16
#define LQ  256
#define LK  256
#define QD  256
#define HD  128
#define VD  128
#define KT  16    // k-rows per CTA; warp w owns k-rows {2w, 2w+1}

// Scratch for projected q/k (allocation-free rule: __device__ globals)
__device__ float g_qp[B_ * LQ * HD];
__device__ float g_kp[B_ * LK * HD];

__device__ __forceinline__ float tanh_fast(float x) {
    float y;
    asm("tanh.approx.f32 %0, %1;" : "=f"(y) : "f"(x));
    return y;
}
__device__ __forceinline__ unsigned long long pk2(float lo, float hi) {
    unsigned long long r;
    asm("mov.b64 %0, {%1, %2};" : "=l"(r) : "f"(lo), "f"(hi));
    return r;
}
__device__ __forceinline__ void upk2(unsigned long long v, float& lo, float& hi) {
    asm("mov.b64 {%0, %1}, %2;" : "=f"(lo), "=f"(hi) : "l"(v));
}
__device__ __forceinline__ void fma2(unsigned long long& d, unsigned long long a,
                                     unsigned long long b) {
    asm("fma.rn.f32x2 %0, %1, %2, %0;" : "+l"(d) : "l"(a), "l"(b));
}

// ============================================================================
// Kernel 1: qp = query @ Wq, kp = key @ Wk   (fp32, packed f32x2 FFMA)
// BM=64, BN=128(all H), BK=32, 256 threads. Thread tile 8 rows x 4 cols
// (rows packed into 4 f32x2 accum pairs). Per kk: 2 bcast LDS.128 (A) +
// 1 lane LDS.128 (B) = 6 wavefronts per 16 FFMA2 -> FFMA/LDS balanced.
// ============================================================================
__global__ __launch_bounds__(256) void proj_kernel(
    const float* __restrict__ q_in, const float* __restrict__ k_in,
    const float* __restrict__ Wq,   const float* __restrict__ Wk)
{
    const float* X = blockIdx.y ? k_in : q_in;
    const float* W = blockIdx.y ? Wk : Wq;
    float* Y       = blockIdx.y ? g_kp : g_qp;

    __shared__ __align__(16) float As[32][68];   // [k][row], stride 272B (16B-aligned)
    __shared__ __align__(16) float Bs[32][128];  // [k][h]

    const int t  = threadIdx.x;
    const int tx = t & 31;          // col group (4 cols)
    const int ty = t >> 5;          // row group (8 rows)
    const int r0 = blockIdx.x * 64;

    unsigned long long acc[4][4];   // [rowpair][col]
    #pragma unroll
    for (int rp = 0; rp < 4; rp++)
        #pragma unroll
        for (int c = 0; c < 4; c++) acc[rp][c] = 0ull;

    for (int kb = 0; kb < QD; kb += 32) {
        __syncthreads();
        // A tile 64x32 (transposed): thread loads 2 float4 along k
        {
            int kk4 = t & 7, r = t >> 3;     // r 0..31
            #pragma unroll
            for (int j = 0; j < 2; j++) {
                int rr = r + 32 * j;
                float4 a4 = *(const float4*)&X[(r0 + rr) * QD + kb + kk4 * 4];
                As[kk4 * 4 + 0][rr] = a4.x;
                As[kk4 * 4 + 1][rr] = a4.y;
                As[kk4 * 4 + 2][rr] = a4.z;
                As[kk4 * 4 + 3][rr] = a4.w;
            }
        }
        // B tile 32x128: 4 float4 per thread
        {
            int h4 = t & 31, kk = t >> 5;
            #pragma unroll
            for (int j = 0; j < 4; j++)
                *(float4*)&Bs[kk + 8 * j][h4 * 4] =
                    *(const float4*)&W[(kb + kk + 8 * j) * HD + h4 * 4];
        }
        __syncthreads();
        #pragma unroll
        for (int kk = 0; kk < 32; kk++) {
            float4 a0 = *(const float4*)&As[kk][ty * 8];       // bcast
            float4 a1 = *(const float4*)&As[kk][ty * 8 + 4];   // bcast
            float4 bv = *(const float4*)&Bs[kk][tx * 4];       // lane-strided
            unsigned long long ap[4] = { pk2(a0.x, a0.y), pk2(a0.z, a0.w),
                                         pk2(a1.x, a1.y), pk2(a1.z, a1.w) };
            unsigned long long bb[4] = { pk2(bv.x, bv.x), pk2(bv.y, bv.y),
                                         pk2(bv.z, bv.z), pk2(bv.w, bv.w) };
            #pragma unroll
            for (int rp = 0; rp < 4; rp++)
                #pragma unroll
                for (int c = 0; c < 4; c++) fma2(acc[rp][c], ap[rp], bb[c]);
        }
    }

    #pragma unroll
    for (int rp = 0; rp < 4; rp++) {
        float lo[4], hi[4];
        #pragma unroll
        for (int c = 0; c < 4; c++) upk2(acc[rp][c], lo[c], hi[c]);
        int r = r0 + ty * 8 + 2 * rp;
        *(float4*)&Y[r * HD + tx * 4]       = make_float4(lo[0], lo[1], lo[2], lo[3]);
        *(float4*)&Y[(r + 1) * HD + tx * 4] = make_float4(hi[0], hi[1], hi[2], hi[3]);
    }
}

// ============================================================================
// Kernel 2: scores + softmax(over q) + context. grid = B*(LK/16) = 256 CTAs.
// Phase B: warp owns 2 k-rows, lane owns 2 q's -> 4 tanh per
//   {LDS.64 qp (2 wf) + LDS.128 bcast (kp0,kp1,v,pad) (1 wf)}: MUFU-bound.
// h processed in 2 halves of 64 (smem budget); q in 4 tiles of 64.
// Scores stay in registers; softmax is warp-local shuffles.
// Phase D: 2q-step, P float2 bcast + 2x LDS.128 value -> 10 wf / 16 FFMA.
// Single 32KB smem union: [qps 64x66 | kps2 64x32] <-> [S 16x256 | val_s 32x128]
// ============================================================================
__global__ __launch_bounds__(256) void attn_kernel(
    const float* __restrict__ value, const float* __restrict__ vvec,
    float* __restrict__ ctx, float* __restrict__ attn)
{
    const int b  = blockIdx.x >> 4;          // 16 k-tiles per batch
    const int k0 = (blockIdx.x & 15) * KT;

    __shared__ __align__(16) float sm[8192];           // 32 KB union
    float* qps   = sm;                // [64][66]  (h-half x q-tile, transposed)
    float* kps2  = sm + 4224;         // [64][32]: pair w -> (kp0, kp1, v, pad)
    float* S     = sm;                // [16][256] softmax'd P
    float* val_s = sm + 4096;         // [32][128] value tile

    const int t    = threadIdx.x;
    const int w    = t >> 5;
    const int lane = t & 31;

    const float* kp_b = g_kp + (size_t)(b * LK + k0) * HD;
    const float* qp_b = g_qp + (size_t)b * LQ * HD;

    float acc[4][2][2];              // [q-pass][k][q]
    #pragma unroll
    for (int p = 0; p < 4; p++)
        #pragma unroll
        for (int kk = 0; kk < 2; kk++) { acc[p][kk][0] = 0.f; acc[p][kk][1] = 0.f; }

    // ---- Phase B: scores ----
    #pragma unroll
    for (int hh = 0; hh < 2; hh++) {
        __syncthreads();
        // stage kp pairs + v: kps2[h][pair*4 + {0,1,2}]
        for (int idx = t; idx < KT * 64; idx += 256) {
            int k = idx >> 6, h = idx & 63;
            kps2[h * 32 + (k >> 1) * 4 + (k & 1)] = kp_b[k * HD + hh * 64 + h];
        }
        for (int idx = t; idx < 8 * 64; idx += 256) {
            int pr = idx >> 6, h = idx & 63;
            kps2[h * 32 + pr * 4 + 2] = vvec[hh * 64 + h];
        }
        #pragma unroll
        for (int p = 0; p < 4; p++) {
            __syncthreads();
            // stage qp tile transposed: qps[h][q], q in [p*64, p*64+64)
            {
                int h4 = t & 15, qr = t >> 4;     // qr 0..15
                #pragma unroll
                for (int j = 0; j < 4; j++) {
                    int q = qr + 16 * j;
                    float4 v4 = *(const float4*)&qp_b[(p * 64 + q) * HD + hh * 64 + h4 * 4];
                    qps[(h4 * 4 + 0) * 66 + q] = v4.x;
                    qps[(h4 * 4 + 1) * 66 + q] = v4.y;
                    qps[(h4 * 4 + 2) * 66 + q] = v4.z;
                    qps[(h4 * 4 + 3) * 66 + q] = v4.w;
                }
            }
            __syncthreads();
            #pragma unroll 16
            for (int h = 0; h < 64; h++) {
                float2 qv = *(const float2*)&qps[h * 66 + 2 * lane];   // 2 wf
                float4 kv = *(const float4*)&kps2[h * 32 + w * 4];     // bcast 1 wf
                acc[p][0][0] += tanh_fast(qv.x + kv.x) * kv.z;
                acc[p][0][1] += tanh_fast(qv.y + kv.x) * kv.z;
                acc[p][1][0] += tanh_fast(qv.x + kv.y) * kv.z;
                acc[p][1][1] += tanh_fast(qv.y + kv.y) * kv.z;
            }
        }
    }
    __syncthreads();   // all phase-B smem reads done before S overlay writes

    // ---- Phase C: softmax over q, warp-local (rows 2w, 2w+1) ----
    #pragma unroll
    for (int kk = 0; kk < 2; kk++) {
        float m = -1e30f;
        #pragma unroll
        for (int p = 0; p < 4; p++)
            m = fmaxf(m, fmaxf(acc[p][kk][0], acc[p][kk][1]));
        #pragma unroll
        for (int o = 16; o > 0; o >>= 1)
            m = fmaxf(m, __shfl_xor_sync(0xffffffffu, m, o));
        float e[4][2], s = 0.f;
        #pragma unroll
        for (int p = 0; p < 4; p++) {
            e[p][0] = __expf(acc[p][kk][0] - m);
            e[p][1] = __expf(acc[p][kk][1] - m);
            s += e[p][0] + e[p][1];
        }
        #pragma unroll
        for (int o = 16; o > 0; o >>= 1)
            s += __shfl_xor_sync(0xffffffffu, s, o);
        float inv = 1.0f / s;
        float* arow = attn + (size_t)(b * LK + k0 + 2 * w + kk) * LQ;
        #pragma unroll
        for (int p = 0; p < 4; p++) {
            float2 pr = make_float2(e[p][0] * inv, e[p][1] * inv);
            *(float2*)&S[(2 * w + kk) * 256 + p * 64 + 2 * lane] = pr;
            *(float2*)&arow[p * 64 + 2 * lane] = pr;
        }
    }

    // ---- Phase D: ctx[k][vd] = sum_q P[k][q] * value[b][q][vd] ----
    float4 c0 = make_float4(0.f, 0.f, 0.f, 0.f);
    float4 c1 = make_float4(0.f, 0.f, 0.f, 0.f);
    const float* val_b = value + (size_t)b * LQ * VD;
    for (int qt = 0; qt < 8; qt++) {
        __syncthreads();
        {   // stage value tile 32x128 (float4)
            int c4 = t & 31, qr = t >> 5;     // qr 0..7
            #pragma unroll
            for (int j = 0; j < 4; j++) {
                int q = qr + 8 * j;
                *(float4*)&val_s[q * VD + c4 * 4] =
                    *(const float4*)&val_b[(qt * 32 + q) * VD + c4 * 4];
            }
        }
        __syncthreads();
        #pragma unroll 8
        for (int qq = 0; qq < 32; qq += 2) {
            float2 P0 = *(const float2*)&S[(2 * w)     * 256 + qt * 32 + qq];  // bcast
            float2 P1 = *(const float2*)&S[(2 * w + 1) * 256 + qt * 32 + qq];  // bcast
            float4 v0 = *(const float4*)&val_s[(qq)     * VD + lane * 4];
            float4 v1 = *(const float4*)&val_s[(qq + 1) * VD + lane * 4];
            c0.x += P0.x * v0.x + P0.y * v1.x;
            c0.y += P0.x * v0.y + P0.y * v1.y;
            c0.z += P0.x * v0.z + P0.y * v1.z;
            c0.w += P0.x * v0.w + P0.y * v1.w;
            c1.x += P1.x * v0.x + P1.y * v1.x;
            c1.y += P1.x * v0.y + P1.y * v1.y;
            c1.z += P1.x * v0.z + P1.y * v1.z;
            c1.w += P1.x * v0.w + P1.y * v1.w;
        }
    }
    *(float4*)&ctx[(size_t)(b * LK + k0 + 2 * w)     * VD + lane * 4] = c0;
    *(float4*)&ctx[(size_t)(b * LK + k0 + 2 * w + 1) * VD + lane * 4] = c1;
}

// ============================================================================
// Launch: inputs (metadata order): query, key, value, Wq, Wk, v
// d_out = context [B,LK,VD] followed by attention [B,LK,LQ]
// ============================================================================
extern "C" void kernel_launch(void* const* d_in, const int* in_sizes, int n_in,
                              void* d_out, int out_size)
{
    const float* query = (const float*)d_in[0];
    const float* key_t = (const float*)d_in[1];
    const float* value = (const float*)d_in[2];
    const float* Wq    = (const float*)d_in[3];
    const float* Wk    = (const float*)d_in[4];
    const float* vvec  = (const float*)d_in[5];

    float* ctx  = (float*)d_out;
    float* attn = ctx + (size_t)B_ * LK * VD;

    dim3 g1((B_ * LQ) / 64, 2);          // 64 x 2 = 128 CTAs
    proj_kernel<<<g1, 256>>>(query, key_t, Wq, Wk);
    attn_kernel<<<B_ * (LK / KT), 256>>>(value, vvec, ctx, attn);
}

// round 8
// speedup vs baseline: 1.2580x; 1.0563x over previous
#include <cuda_runtime.h>
#include <cuda_fp16.h>
#include <cuda_bf16.h>

#define B_  16
#define LQ  256
#define LK  256
#define QD  256
#define HD  128
#define VD  128
#define KT  8     // k-rows per CTA; 4 warps, warp w owns k-rows {2w, 2w+1}

// f16 projected q/k, TRANSPOSED per batch: [b][h][q] / [b][h][k]
__device__ __half g_qpT[B_ * HD * LQ];
__device__ __half g_kpT[B_ * HD * LK];

namespace {  // anonymous: internal linkage, immune to library-name collisions

__device__ __forceinline__ __half2 tanh_h2_(__half2 x) {
    unsigned xo, xi = *(unsigned*)&x;
    asm("tanh.approx.f16x2 %0, %1;" : "=r"(xo) : "r"(xi));
    return *(__half2*)&xo;
}
__device__ __forceinline__ unsigned long long pk2_(float lo, float hi) {
    unsigned long long r;
    asm("mov.b64 %0, {%1, %2};" : "=l"(r) : "f"(lo), "f"(hi));
    return r;
}
__device__ __forceinline__ void upk2_(unsigned long long v, float& lo, float& hi) {
    asm("mov.b64 {%0, %1}, %2;" : "=f"(lo), "=f"(hi) : "l"(v));
}
__device__ __forceinline__ void fma2_(unsigned long long& d, unsigned long long a,
                                      unsigned long long b) {
    asm("fma.rn.f32x2 %0, %1, %2, %0;" : "+l"(d) : "l"(a), "l"(b));
}

}  // namespace

// ============================================================================
// Kernel 1: qp = query @ Wq, kp = key @ Wk  (fp32 math, f32x2 FFMA,
// epilogue converts to f16 and stores TRANSPOSED [b][h][row]).
// BM=64, BN=128, BK=32, 256 threads; thread tile 8 rows x 4 cols.
// ============================================================================
__global__ __launch_bounds__(256) void proj_kernel(
    const float* __restrict__ q_in, const float* __restrict__ k_in,
    const float* __restrict__ Wq,   const float* __restrict__ Wk)
{
    const float* X  = blockIdx.y ? k_in : q_in;
    const float* W  = blockIdx.y ? Wk : Wq;
    __half*      YT = blockIdx.y ? g_kpT : g_qpT;

    __shared__ __align__(16) float As[32][68];
    __shared__ __align__(16) float Bs[32][128];

    const int t  = threadIdx.x;
    const int tx = t & 31;
    const int ty = t >> 5;
    const int r0 = blockIdx.x * 64;          // 64 rows, all within one batch

    unsigned long long acc[4][4];
    #pragma unroll
    for (int rp = 0; rp < 4; rp++)
        #pragma unroll
        for (int c = 0; c < 4; c++) acc[rp][c] = 0ull;

    for (int kb = 0; kb < QD; kb += 32) {
        __syncthreads();
        {   // A tile 64x32 transposed
            int kk4 = t & 7, r = t >> 3;
            #pragma unroll
            for (int j = 0; j < 2; j++) {
                int rr = r + 32 * j;
                float4 a4 = *(const float4*)&X[(r0 + rr) * QD + kb + kk4 * 4];
                As[kk4 * 4 + 0][rr] = a4.x;
                As[kk4 * 4 + 1][rr] = a4.y;
                As[kk4 * 4 + 2][rr] = a4.z;
                As[kk4 * 4 + 3][rr] = a4.w;
            }
        }
        {   // B tile 32x128
            int h4 = t & 31, kk = t >> 5;
            #pragma unroll
            for (int j = 0; j < 4; j++)
                *(float4*)&Bs[kk + 8 * j][h4 * 4] =
                    *(const float4*)&W[(kb + kk + 8 * j) * HD + h4 * 4];
        }
        __syncthreads();
        #pragma unroll
        for (int kk = 0; kk < 32; kk++) {
            float4 a0 = *(const float4*)&As[kk][ty * 8];
            float4 a1 = *(const float4*)&As[kk][ty * 8 + 4];
            float4 bv = *(const float4*)&Bs[kk][tx * 4];
            unsigned long long ap[4] = { pk2_(a0.x, a0.y), pk2_(a0.z, a0.w),
                                         pk2_(a1.x, a1.y), pk2_(a1.z, a1.w) };
            unsigned long long bb[4] = { pk2_(bv.x, bv.x), pk2_(bv.y, bv.y),
                                         pk2_(bv.z, bv.z), pk2_(bv.w, bv.w) };
            #pragma unroll
            for (int rp = 0; rp < 4; rp++)
                #pragma unroll
                for (int c = 0; c < 4; c++) fma2_(acc[rp][c], ap[rp], bb[c]);
        }
    }

    // Epilogue: per col c (= h), 8 contiguous rows -> 4 half2 -> one STG.128
    const int bb   = r0 / LQ;
    const int qloc = (r0 % LQ) + ty * 8;
    #pragma unroll
    for (int c = 0; c < 4; c++) {
        int h = tx * 4 + c;
        float lo[4], hi[4];
        #pragma unroll
        for (int rp = 0; rp < 4; rp++) upk2_(acc[rp][c], lo[rp], hi[rp]);
        __half2 p0 = __floats2half2_rn(lo[0], hi[0]);
        __half2 p1 = __floats2half2_rn(lo[1], hi[1]);
        __half2 p2 = __floats2half2_rn(lo[2], hi[2]);
        __half2 p3 = __floats2half2_rn(lo[3], hi[3]);
        uint4 out = make_uint4(*(unsigned*)&p0, *(unsigned*)&p1,
                               *(unsigned*)&p2, *(unsigned*)&p3);
        *(uint4*)&YT[(bb * HD + h) * LQ + qloc] = out;
    }
}

// ============================================================================
// Kernel 2: scores (f16x2 MUFU) + softmax(over q) + context.
// grid = B*(LK/8) = 512 CTAs, 128 threads (4 warps). Warp w: k-rows {2w,2w+1};
// lane: q's {2*lane, 2*lane+1} packed as the f16x2 lanes.
// Per h per warp: LDS.32 qp(half2) + LDS.128 bcast {kp0dup,kp1dup,vdup}
//   -> 2 HADD2 + 2 tanh.f16x2 + 2 HFMA2 = 4 tanh / 2 MUFU instr. MUFU-bound.
// f16 partial accs flushed to f32 every 8 h. Softmax warp-local.
// smem union (24.6KB): [qps half2 64x36u | kvs uint4 64x4] <-> [S 8x256 | val_s 32x128]
// ============================================================================
__global__ __launch_bounds__(128) void attn_kernel(
    const float* __restrict__ value, const float* __restrict__ vvec,
    float* __restrict__ ctx, float* __restrict__ attn)
{
    const int b  = blockIdx.x >> 5;          // 32 k-tiles per batch
    const int k0 = (blockIdx.x & 31) * KT;

    __shared__ __align__(16) float sm[6144];           // 24576 B union
    unsigned* qps = (unsigned*)sm;                      // [64][36] half2 (9216 B)
    uint4*    kvs = (uint4*)((char*)sm + 9216);         // [64][4]  (4096 B)
    float*    S     = sm;                               // [8][256] (8192 B)
    float*    val_s = sm + 2048;                        // [32][128] (16384 B)

    const int t    = threadIdx.x;
    const int w    = t >> 5;
    const int lane = t & 31;

    const __half* kpT = g_kpT + (size_t)b * HD * LK;
    const __half* qpT = g_qpT + (size_t)b * HD * LQ;

    float accf[4][2][2];             // [q-pass][k][q]
    #pragma unroll
    for (int p = 0; p < 4; p++)
        #pragma unroll
        for (int kk = 0; kk < 2; kk++) { accf[p][kk][0] = 0.f; accf[p][kk][1] = 0.f; }

    // ---- Phase B ----
    #pragma unroll
    for (int hh = 0; hh < 2; hh++) {
        __syncthreads();   // prior readers of kvs done
        // stage kvs[h][w] = {dup(kp[2w]), dup(kp[2w+1]), dup(v), pad}
        #pragma unroll
        for (int j = 0; j < 2; j++) {
            int idx = t + 128 * j;                 // 256 entries
            int h = idx >> 2, ww = idx & 3;
            __half2 kk2 = *(const __half2*)&kpT[(hh * 64 + h) * LK + k0 + 2 * ww];
            __half2 vd  = __float2half2_rn(vvec[hh * 64 + h]);
            __half2 k0d = __low2half2(kk2), k1d = __high2half2(kk2);
            kvs[idx] = make_uint4(*(unsigned*)&k0d, *(unsigned*)&k1d,
                                  *(unsigned*)&vd, 0u);
        }
        #pragma unroll
        for (int p = 0; p < 4; p++) {
            __syncthreads();
            // stage qps[h][qpair]: 512 uint4 copies (8 q's each)
            #pragma unroll
            for (int j = 0; j < 4; j++) {
                int idx = t + 128 * j;
                int h = idx >> 3, q4 = idx & 7;
                uint4 src = *(const uint4*)&qpT[(hh * 64 + h) * LQ + p * 64 + q4 * 8];
                ((uint4*)(qps + h * 36))[q4] = src;
            }
            __syncthreads();
            #pragma unroll
            for (int h8 = 0; h8 < 64; h8 += 8) {
                __half2 a0 = __float2half2_rn(0.f), a1 = a0;
                #pragma unroll
                for (int j = 0; j < 8; j++) {
                    int h = h8 + j;
                    unsigned qu = qps[h * 36 + lane];
                    __half2 qv = *(__half2*)&qu;
                    uint4 kv = kvs[h * 4 + w];                  // bcast
                    __half2 kp0 = *(__half2*)&kv.x;
                    __half2 kp1 = *(__half2*)&kv.y;
                    __half2 vd  = *(__half2*)&kv.z;
                    a0 = __hfma2(tanh_h2_(__hadd2(qv, kp0)), vd, a0);
                    a1 = __hfma2(tanh_h2_(__hadd2(qv, kp1)), vd, a1);
                }
                accf[p][0][0] += __low2float(a0);
                accf[p][0][1] += __high2float(a0);
                accf[p][1][0] += __low2float(a1);
                accf[p][1][1] += __high2float(a1);
            }
        }
    }
    __syncthreads();   // phase-B smem reads done before S overlay

    // ---- Phase C: softmax over q, warp-local ----
    #pragma unroll
    for (int kk = 0; kk < 2; kk++) {
        float m = -1e30f;
        #pragma unroll
        for (int p = 0; p < 4; p++)
            m = fmaxf(m, fmaxf(accf[p][kk][0], accf[p][kk][1]));
        #pragma unroll
        for (int o = 16; o > 0; o >>= 1)
            m = fmaxf(m, __shfl_xor_sync(0xffffffffu, m, o));
        float e[4][2], s = 0.f;
        #pragma unroll
        for (int p = 0; p < 4; p++) {
            e[p][0] = __expf(accf[p][kk][0] - m);
            e[p][1] = __expf(accf[p][kk][1] - m);
            s += e[p][0] + e[p][1];
        }
        #pragma unroll
        for (int o = 16; o > 0; o >>= 1)
            s += __shfl_xor_sync(0xffffffffu, s, o);
        float inv = 1.0f / s;
        float* arow = attn + (size_t)(b * LK + k0 + 2 * w + kk) * LQ;
        #pragma unroll
        for (int p = 0; p < 4; p++) {
            float2 pr = make_float2(e[p][0] * inv, e[p][1] * inv);
            *(float2*)&S[(2 * w + kk) * 256 + p * 64 + 2 * lane] = pr;
            *(float2*)&arow[p * 64 + 2 * lane] = pr;
        }
    }

    // ---- Phase D: ctx[k][vd] = sum_q P[k][q] * value[b][q][vd] ----
    float4 c0 = make_float4(0.f, 0.f, 0.f, 0.f);
    float4 c1 = make_float4(0.f, 0.f, 0.f, 0.f);
    const float* val_b = value + (size_t)b * LQ * VD;
    for (int qt = 0; qt < 8; qt++) {
        __syncthreads();
        #pragma unroll
        for (int j = 0; j < 8; j++) {          // stage 32x128 value tile
            int idx = t + 128 * j;             // 1024 float4
            int q = idx >> 5, c4 = idx & 31;
            *(float4*)&val_s[q * VD + c4 * 4] =
                *(const float4*)&val_b[(qt * 32 + q) * VD + c4 * 4];
        }
        __syncthreads();
        #pragma unroll
        for (int qq4 = 0; qq4 < 8; qq4++) {    // 4 q per step
            float4 P0 = *(const float4*)&S[(2 * w)     * 256 + qt * 32 + qq4 * 4];
            float4 P1 = *(const float4*)&S[(2 * w + 1) * 256 + qt * 32 + qq4 * 4];
            const float pa0[4] = { P0.x, P0.y, P0.z, P0.w };
            const float pa1[4] = { P1.x, P1.y, P1.z, P1.w };
            #pragma unroll
            for (int u = 0; u < 4; u++) {
                float4 vv = *(const float4*)&val_s[(qq4 * 4 + u) * VD + lane * 4];
                c0.x += pa0[u] * vv.x; c0.y += pa0[u] * vv.y;
                c0.z += pa0[u] * vv.z; c0.w += pa0[u] * vv.w;
                c1.x += pa1[u] * vv.x; c1.y += pa1[u] * vv.y;
                c1.z += pa1[u] * vv.z; c1.w += pa1[u] * vv.w;
            }
        }
    }
    *(float4*)&ctx[(size_t)(b * LK + k0 + 2 * w)     * VD + lane * 4] = c0;
    *(float4*)&ctx[(size_t)(b * LK + k0 + 2 * w + 1) * VD + lane * 4] = c1;
}

// ============================================================================
// Launch: inputs: query, key, value, Wq, Wk, v
// d_out = context [B,LK,VD] followed by attention [B,LK,LQ]
// ============================================================================
extern "C" void kernel_launch(void* const* d_in, const int* in_sizes, int n_in,
                              void* d_out, int out_size)
{
    const float* query = (const float*)d_in[0];
    const float* key_t = (const float*)d_in[1];
    const float* value = (const float*)d_in[2];
    const float* Wq    = (const float*)d_in[3];
    const float* Wk    = (const float*)d_in[4];
    const float* vvec  = (const float*)d_in[5];

    float* ctx  = (float*)d_out;
    float* attn = ctx + (size_t)B_ * LK * VD;

    dim3 g1((B_ * LQ) / 64, 2);
    proj_kernel<<<g1, 256>>>(query, key_t, Wq, Wk);
    attn_kernel<<<B_ * (LK / KT), 128>>>(value, vvec, ctx, attn);
}